// round 15
// baseline (speedup 1.0000x reference)
#include <cuda_runtime.h>
#include <cuda_bf16.h>
#include <math.h>

#define BB 64
#define CC 2048
#define QQ 128
#define DD 128
#define CT 64
#define NSPLIT 4
#define MASKV (-1e30f)
#define SA 132    // packed A-tile word stride
#define SB 136    // packed B-tile word stride
#define SMA 18    // mid stT word stride
#define NTHR 512

// ----------------------------------------------------------------------------
// Device scratch
// ----------------------------------------------------------------------------
__device__ float    g_score[(size_t)BB * CC * QQ];  // E = exp(raw score)
__device__ float    g_rc[BB * CC];
__device__ float    g_cq[BB * QQ];
__device__ float    g_colsum[BB * QQ];
__device__ float    g_mid[BB * QQ * DD];
__device__ float    g_pproj[BB * DD];               // pooled proj + cqa_b@ccW1.T + cc_b
__device__ unsigned g_midp[BB * QQ * DD];           // packed (mid/colsum)
__device__ unsigned g_qfTp[BB * DD * QQ];           // packed qfeats^T [b][d][q]
__device__ unsigned g_qfp[BB * QQ * DD];            // packed qfeats  [b][q][d]
__device__ unsigned g_vfp[(size_t)BB * CC * DD];    // packed vfeats
__device__ unsigned g_vmlup[(size_t)BB * CC * DD];  // packed vfeats*w4mlu
__device__ unsigned g_GWp[4 * DD * DD];             // packed G=ccW1@cqa_W: [part][k][d]

// ----------------------------------------------------------------------------
// bf16-split helpers
// ----------------------------------------------------------------------------
__device__ __forceinline__ unsigned pack_bf(float x) {
    unsigned h = (unsigned)__bfloat16_as_ushort(__float2bfloat16(x));
    float hf = __uint_as_float(h << 16);
    unsigned l = (unsigned)__bfloat16_as_ushort(__float2bfloat16(x - hf));
    return h | (l << 16);
}

__device__ __forceinline__ float unpack_bf(unsigned w) {
    return __uint_as_float(w << 16) + __uint_as_float(w & 0xffff0000u);
}

__device__ __forceinline__ void mma_bf16(float c[4], const unsigned a[4], const unsigned b[2]) {
    asm volatile(
        "mma.sync.aligned.m16n8k16.row.col.f32.bf16.bf16.f32 "
        "{%0,%1,%2,%3}, {%4,%5,%6,%7}, {%8,%9}, {%0,%1,%2,%3};"
        : "+f"(c[0]), "+f"(c[1]), "+f"(c[2]), "+f"(c[3])
        : "r"(a[0]), "r"(a[1]), "r"(a[2]), "r"(a[3]), "r"(b[0]), "r"(b[1]));
}

__device__ __forceinline__ unsigned s2u(const void* p) {
    unsigned r;
    asm("{.reg .u64 t; cvta.to.shared.u64 t, %1; cvt.u32.u64 %0, t;}" : "=r"(r) : "l"(p));
    return r;
}
__device__ __forceinline__ void cp16(unsigned smaddr, const void* g) {
    asm volatile("cp.async.cg.shared.global [%0], [%1], 16;" :: "r"(smaddr), "l"(g));
}
#define CP_COMMIT() asm volatile("cp.async.commit_group;" ::: "memory")
#define CP_WAIT1()  asm volatile("cp.async.wait_group 1;" ::: "memory")

// Warp computes C[wr0:wr0+16][wc0:wc0+NT*8] += A(:, koff:koff+K) @ B(K rows).
// Single 16-row fragment block per warp (16 warps cover the CTA tile).
template <int NT, int SAs, int SBs, int K>
__device__ __forceinline__ void mma_stage_1(const unsigned* __restrict__ A,
                                            const unsigned* __restrict__ B,
                                            float acc[NT][4],
                                            int wr0, int wc0, int lane, int koff) {
    const int gr = lane >> 2, t2 = (lane & 3) * 2;
#pragma unroll
    for (int k0 = 0; k0 < K; k0 += 16) {
        unsigned ah[4], al[4];
        const unsigned* p0 = A + (wr0 + gr) * SAs + koff + k0 + t2;
        const unsigned* p1 = A + (wr0 + 8 + gr) * SAs + koff + k0 + t2;
        uint2 wa = *(const uint2*)p0;
        uint2 wb = *(const uint2*)p1;
        uint2 wc = *(const uint2*)(p0 + 8);
        uint2 wd = *(const uint2*)(p1 + 8);
        ah[0] = __byte_perm(wa.x, wa.y, 0x5410); al[0] = __byte_perm(wa.x, wa.y, 0x7632);
        ah[1] = __byte_perm(wb.x, wb.y, 0x5410); al[1] = __byte_perm(wb.x, wb.y, 0x7632);
        ah[2] = __byte_perm(wc.x, wc.y, 0x5410); al[2] = __byte_perm(wc.x, wc.y, 0x7632);
        ah[3] = __byte_perm(wd.x, wd.y, 0x5410); al[3] = __byte_perm(wd.x, wd.y, 0x7632);
#pragma unroll
        for (int nt = 0; nt < NT; nt++) {
            int n = wc0 + nt * 8 + gr;
            unsigned v0 = B[(k0 + t2) * SBs + n];
            unsigned v1 = B[(k0 + t2 + 1) * SBs + n];
            unsigned v2 = B[(k0 + 8 + t2) * SBs + n];
            unsigned v3 = B[(k0 + 9 + t2) * SBs + n];
            unsigned bh[2] = {__byte_perm(v0, v1, 0x5410), __byte_perm(v2, v3, 0x5410)};
            unsigned bl[2] = {__byte_perm(v0, v1, 0x7632), __byte_perm(v2, v3, 0x7632)};
            mma_bf16(acc[nt], ah, bh);
            mma_bf16(acc[nt], al, bh);
            mma_bf16(acc[nt], ah, bl);
        }
    }
}

// ----------------------------------------------------------------------------
// Prep kernels
// ----------------------------------------------------------------------------
__global__ void prep_G(const float* __restrict__ cqa_W, const float* __restrict__ cc_W) {
    __shared__ float s_col[DD];
    int col = blockIdx.x;
    int d = threadIdx.x;
    s_col[d] = cqa_W[d * (4 * DD) + col];
    __syncthreads();
    float s = 0.f;
#pragma unroll 4
    for (int j = 0; j < DD; j++) s += cc_W[d * (2 * DD) + j] * s_col[j];
    g_GWp[col * DD + d] = pack_bf(s);
}

__global__ void prep_qf(const float* __restrict__ qf) {
    int i = blockIdx.x * blockDim.x + threadIdx.x;
    if (i >= BB * DD * QQ) return;
    int q = i % QQ;
    int t = i / QQ;
    int d = t % DD;
    int b = t / DD;
    g_qfTp[i] = pack_bf(qf[((size_t)(b * QQ + q)) * DD + d]);
    g_qfp[i] = pack_bf(qf[i]);
}

// warp-per-row: pack vfeats + vfeats*mlu, and rc dot product, one pass
__global__ void prep_vf_rc(const float* __restrict__ vf, const float* __restrict__ w4mlu,
                           const float* __restrict__ w4C) {
    int row = blockIdx.x * 8 + (threadIdx.x >> 5);
    int lane = threadIdx.x & 31;
    float4 t = *(const float4*)(vf + (size_t)row * DD + lane * 4);
    float4 m = *(const float4*)(w4mlu + lane * 4);
    float4 w = *(const float4*)(w4C + lane * 4);
    unsigned* vp = g_vfp + (size_t)row * DD + lane * 4;
    unsigned* mp = g_vmlup + (size_t)row * DD + lane * 4;
    vp[0] = pack_bf(t.x); vp[1] = pack_bf(t.y); vp[2] = pack_bf(t.z); vp[3] = pack_bf(t.w);
    mp[0] = pack_bf(t.x * m.x); mp[1] = pack_bf(t.y * m.y);
    mp[2] = pack_bf(t.z * m.z); mp[3] = pack_bf(t.w * m.w);
    float s = t.x * w.x + t.y * w.y + t.z * w.z + t.w * w.w;
#pragma unroll
    for (int off = 16; off > 0; off >>= 1) s += __shfl_xor_sync(0xffffffffu, s, off);
    if (lane == 0) g_rc[row] = s;
}

__global__ void prep_cq(const float* __restrict__ qf, const float* __restrict__ w4Q) {
    int row = blockIdx.x * 8 + (threadIdx.x >> 5);
    int lane = threadIdx.x & 31;
    float4 t = *(const float4*)(qf + (size_t)row * DD + lane * 4);
    float4 w = *(const float4*)(w4Q + lane * 4);
    float s = t.x * w.x + t.y * w.y + t.z * w.z + t.w * w.w;
#pragma unroll
    for (int off = 16; off > 0; off >>= 1) s += __shfl_xor_sync(0xffffffffu, s, off);
    if (lane == 0) g_cq[row] = s;
}

__global__ void zero_k() {
    int i = blockIdx.x * blockDim.x + threadIdx.x;
    if (i < BB * QQ * DD) g_mid[i] = 0.f;
    if (i < BB * QQ) g_colsum[i] = 0.f;
}

__global__ void pack_mid() {
    int i = blockIdx.x * blockDim.x + threadIdx.x;
    if (i >= BB * QQ * DD) return;
    int q = (i >> 7) & (QQ - 1);
    int b = i >> 14;
    g_midp[i] = pack_bf(g_mid[i] * (1.f / g_colsum[b * QQ + q]));
}

// ----------------------------------------------------------------------------
// Pooled projection (+ folded cqa_b @ ccW1.T + cc_b)
// ----------------------------------------------------------------------------
__global__ void pooled_kernel(const float* __restrict__ qf, const float* __restrict__ qmask,
                              const float* __restrict__ wp, const float* __restrict__ cc_W,
                              const float* __restrict__ cc_b, const float* __restrict__ cqa_b) {
    __shared__ float sred[QQ];
    __shared__ float s_al[QQ];
    __shared__ float s_pool[DD];
    int b = blockIdx.x, t = threadIdx.x;

    const float* row = qf + (size_t)(b * QQ + t) * DD;
    float x = 0.f;
#pragma unroll 4
    for (int d = 0; d < DD; d++) x += row[d] * wp[d];
    x += (1.f - qmask[b * QQ + t]) * MASKV;

    sred[t] = x; __syncthreads();
    for (int s = 64; s > 0; s >>= 1) {
        if (t < s) sred[t] = fmaxf(sred[t], sred[t + s]);
        __syncthreads();
    }
    float m = sred[0]; __syncthreads();
    float e = __expf(x - m);
    sred[t] = e; __syncthreads();
    for (int s = 64; s > 0; s >>= 1) {
        if (t < s) sred[t] += sred[t + s];
        __syncthreads();
    }
    float inv = 1.f / sred[0];
    s_al[t] = e * inv; __syncthreads();

    float p = 0.f;
#pragma unroll 4
    for (int q = 0; q < QQ; q++) p += s_al[q] * qf[(size_t)(b * QQ + q) * DD + t];
    s_pool[t] = p; __syncthreads();

    float o = cc_b[t];
#pragma unroll 4
    for (int k = 0; k < DD; k++) {
        o += s_pool[k] * cc_W[t * (2 * DD) + DD + k];
        o += cqa_b[k] * cc_W[t * (2 * DD) + k];
    }
    g_pproj[b * DD + t] = o;
}

// ----------------------------------------------------------------------------
// Score kernel (512 thr, 16 warps): E = exp(score), + masked column sums
// ----------------------------------------------------------------------------
__global__ __launch_bounds__(NTHR) void score_kernel(const float* __restrict__ vmask) {
    extern __shared__ unsigned su[];
    unsigned* sAp = su;               // [64][SA]
    unsigned* sBp = su + CT * SA;     // [128][SB]

    int b = blockIdx.y, c0 = blockIdx.x * CT, tid = threadIdx.x;

    {
        const uint4* srcA = (const uint4*)(g_vmlup + (size_t)(b * CC + c0) * DD);
        for (int i = tid; i < CT * DD / 4; i += NTHR)
            *(uint4*)&sAp[(i >> 5) * SA + (i & 31) * 4] = srcA[i];
        const uint4* srcB = (const uint4*)(g_qfTp + (size_t)b * DD * QQ);
        for (int i = tid; i < DD * QQ / 4; i += NTHR)
            *(uint4*)&sBp[(i >> 5) * SB + (i & 31) * 4] = srcB[i];
    }
    __syncthreads();

    int warp = tid >> 5, lane = tid & 31;
    int gr = lane >> 2, tg = lane & 3;
    int wr0 = (warp & 3) * 16, wc0 = (warp >> 2) * 32;

    float acc[4][4];
#pragma unroll
    for (int nt = 0; nt < 4; nt++)
#pragma unroll
        for (int j = 0; j < 4; j++) acc[nt][j] = 0.f;

    mma_stage_1<4, SA, SB, 128>(sAp, sBp, acc, wr0, wc0, lane, 0);

    int r = wr0 + gr;
    float vm0 = vmask[b * CC + c0 + r];
    float vm1 = vmask[b * CC + c0 + r + 8];
    float rc0 = g_rc[b * CC + c0 + r];
    float rc1 = g_rc[b * CC + c0 + r + 8];

#pragma unroll
    for (int nt = 0; nt < 4; nt++) {
        int q = wc0 + nt * 8 + 2 * tg;
        float cq0 = g_cq[b * QQ + q], cq1 = g_cq[b * QQ + q + 1];
        acc[nt][0] = __expf(acc[nt][0] + rc0 + cq0);
        acc[nt][1] = __expf(acc[nt][1] + rc0 + cq1);
        acc[nt][2] = __expf(acc[nt][2] + rc1 + cq0);
        acc[nt][3] = __expf(acc[nt][3] + rc1 + cq1);
        float* d0 = g_score + ((size_t)(b * CC + c0 + r)) * QQ + q;
        float* d1 = g_score + ((size_t)(b * CC + c0 + r + 8)) * QQ + q;
        *(float2*)d0 = make_float2(acc[nt][0], acc[nt][1]);
        *(float2*)d1 = make_float2(acc[nt][2], acc[nt][3]);
    }

#pragma unroll
    for (int nt = 0; nt < 4; nt++) {
#pragma unroll
        for (int j = 0; j < 2; j++) {
            float cs = acc[nt][j] * vm0 + acc[nt][j + 2] * vm1;
            cs += __shfl_xor_sync(0xffffffffu, cs, 4);
            cs += __shfl_xor_sync(0xffffffffu, cs, 8);
            cs += __shfl_xor_sync(0xffffffffu, cs, 16);
            if (lane < 4)
                atomicAdd(&g_colsum[b * QQ + wc0 + nt * 8 + 2 * tg + j], cs);
        }
    }
}

// ----------------------------------------------------------------------------
// mid(unscaled)[q,d] = sum_c E[c,q]*vmask[c]*v[c,d]  (512 thr, 16 warps)
// ----------------------------------------------------------------------------
__global__ __launch_bounds__(NTHR) void mid_kernel(const float* __restrict__ vmask) {
    __shared__ unsigned u_stT[QQ * SMA];
    __shared__ unsigned u_v[16 * SB];
    int b = blockIdx.x, sp = blockIdx.y, tid = threadIdx.x;
    int cbase = sp * (CC / NSPLIT);
    int warp = tid >> 5, lane = tid & 31;
    int gr = lane >> 2, tg = lane & 3;
    int wr0 = (warp & 7) * 16, wc0 = (warp >> 3) * 64;

    float acc[8][4];
#pragma unroll
    for (int nt = 0; nt < 8; nt++)
#pragma unroll
        for (int j = 0; j < 4; j++) acc[nt][j] = 0.f;

    for (int cc0 = 0; cc0 < CC / NSPLIT; cc0 += 16) {
        __syncthreads();
        for (int i = tid; i < 16 * QQ; i += NTHR) {
            int kc = i >> 7, col = i & 127;
            int c = cbase + cc0 + kc;
            float e = g_score[((size_t)(b * CC + c)) * QQ + col] * vmask[b * CC + c];
            u_stT[col * SMA + kc] = pack_bf(e);
        }
        const uint4* sv = (const uint4*)(g_vfp + (size_t)(b * CC + cbase + cc0) * DD);
        for (int i = tid; i < 16 * DD / 4; i += NTHR)
            *(uint4*)&u_v[(i >> 5) * SB + (i & 31) * 4] = sv[i];
        __syncthreads();
        mma_stage_1<8, SMA, SB, 16>(u_stT, u_v, acc, wr0, wc0, lane, 0);
    }

    int q = wr0 + gr;
#pragma unroll
    for (int nt = 0; nt < 8; nt++) {
        int d = wc0 + nt * 8 + 2 * tg;
        atomicAdd(&g_mid[(size_t)(b * QQ + q) * DD + d],     acc[nt][0]);
        atomicAdd(&g_mid[(size_t)(b * QQ + q) * DD + d + 1], acc[nt][1]);
        atomicAdd(&g_mid[(size_t)(b * QQ + q + 8) * DD + d],     acc[nt][2]);
        atomicAdd(&g_mid[(size_t)(b * QQ + q + 8) * DD + d + 1], acc[nt][3]);
    }
}

// ----------------------------------------------------------------------------
// Mega-fused v4 (512 thr, 16 warps): cp.async double-buffered B, 12 slots
// Slot s: B-matrix m = s>>1 (qf, midp, G0..G3), half h = s&1
// A per slot: [sc,sc, sc,sc, v,v, c2q,c2q, v*c2q,v*c2q, v*q2c,v*q2c]
// ----------------------------------------------------------------------------
__global__ __launch_bounds__(NTHR, 1) void fused_kernel(const float* __restrict__ qmask,
                                                        float* __restrict__ out) {
    extern __shared__ unsigned su[];
    unsigned* u_sc  = su;                 // [64][SA] sc -> v*c2q
    unsigned* u_v   = u_sc + CT * SA;     // [64][SA]
    unsigned* u_c2q = u_v + CT * SA;      // [64][SA]
    unsigned* u_q2c = u_c2q + CT * SA;    // [64][SA] -> v*q2c
    unsigned* u_B   = u_q2c + CT * SA;    // 2 x [64][SB] ping-pong

    int b = blockIdx.y;
    int c0 = blockIdx.x * CT;
    int tid = threadIdx.x;
    int warp = tid >> 5, lane = tid & 31;
    int gr = lane >> 2, tg = lane & 3;
    int wr0 = (warp & 3) * 16, wc0 = (warp >> 2) * 32;

    const unsigned* bsrc[6];
    bsrc[0] = g_qfp + (size_t)b * QQ * DD;
    bsrc[1] = g_midp + (size_t)b * QQ * DD;
    bsrc[2] = g_GWp;
    bsrc[3] = g_GWp + DD * DD;
    bsrc[4] = g_GWp + 2 * DD * DD;
    bsrc[5] = g_GWp + 3 * DD * DD;

#define FILL_HALF(slot, buf)                                                     \
    {                                                                            \
        const unsigned* src_ = bsrc[(slot) >> 1] + (((slot) & 1) * 64) * DD;     \
        unsigned* dstb_ = u_B + (buf) * (64 * SB);                               \
        for (int i = tid; i < 64 * DD / 4; i += NTHR)                            \
            cp16(s2u(&dstb_[(i >> 5) * SB + (i & 31) * 4]), &src_[i * 4]);       \
    }

    // Prologue
    {
        const unsigned* vs = g_vfp + (size_t)(b * CC + c0) * DD;
        for (int i = tid; i < CT * DD / 4; i += NTHR)
            cp16(s2u(&u_v[(i >> 5) * SA + (i & 31) * 4]), &vs[i * 4]);
        FILL_HALF(0, 0)
        CP_COMMIT();
        FILL_HALF(1, 1)
        CP_COMMIT();
    }

    // Phase 0: row softmax from E -> packed u_sc (overlaps async fills)
    {
        float qm[4];
#pragma unroll
        for (int j = 0; j < 4; j++) qm[j] = qmask[b * QQ + lane + 32 * j];
#pragma unroll
        for (int rr = 0; rr < 4; rr++) {
            int r = warp * 4 + rr;
            const float* src = g_score + ((size_t)(b * CC + c0 + r)) * QQ;
            float em[4];
            float s = 0.f;
#pragma unroll
            for (int j = 0; j < 4; j++) { em[j] = src[lane + 32 * j] * qm[j]; s += em[j]; }
#pragma unroll
            for (int off = 16; off > 0; off >>= 1)
                s += __shfl_xor_sync(0xffffffffu, s, off);
            float inv = 1.f / s;
#pragma unroll
            for (int j = 0; j < 4; j++)
                u_sc[r * SA + lane + 32 * j] = pack_bf(em[j] * inv);
        }
    }

#define ZERO_ACC(A_)                                      \
    _Pragma("unroll") for (int nt = 0; nt < 4; nt++)      \
    _Pragma("unroll") for (int j = 0; j < 4; j++) A_[nt][j] = 0.f;

#define PACK_ACC(DST, A_)                                                       \
    {                                                                           \
        int r_ = wr0 + gr;                                                      \
        _Pragma("unroll") for (int nt = 0; nt < 4; nt++) {                      \
            int cI = wc0 + nt * 8 + 2 * tg;                                     \
            (DST)[r_ * SA + cI]           = pack_bf(A_[nt][0]);                 \
            (DST)[r_ * SA + cI + 1]       = pack_bf(A_[nt][1]);                 \
            (DST)[(r_ + 8) * SA + cI]     = pack_bf(A_[nt][2]);                 \
            (DST)[(r_ + 8) * SA + cI + 1] = pack_bf(A_[nt][3]);                 \
        }                                                                       \
    }

    float acc1[4][4], acc2[4][4], oacc[4][4];
    ZERO_ACC(acc1)
    ZERO_ACC(acc2)

#define SLOT(i, Atile, ACC)                                                     \
    CP_WAIT1();                                                                 \
    __syncthreads();                                                            \
    mma_stage_1<4, SA, SB, 64>(Atile, u_B + ((i) & 1) * (64 * SB), ACC,         \
                               wr0, wc0, lane, ((i) & 1) * 64);                 \
    __syncthreads();                                                            \
    if ((i) + 2 < 12) { FILL_HALF((i) + 2, (i) & 1) }                           \
    CP_COMMIT();

    SLOT(0, u_sc, acc1)
    SLOT(1, u_sc, acc1)
    // c2q complete -> pack into u_c2q (read at slots 6,7; syncs intervene)
    PACK_ACC(u_c2q, acc1)
    SLOT(2, u_sc, acc2)
    SLOT(3, u_sc, acc2)
    // q2c complete: v*q2c from regs -> u_q2c; v*c2q pass -> u_sc (sc dead)
    {
        int r = wr0 + gr;
#pragma unroll
        for (int nt = 0; nt < 4; nt++) {
            int cI = wc0 + nt * 8 + 2 * tg;
            u_q2c[r * SA + cI]           = pack_bf(unpack_bf(u_v[r * SA + cI]) * acc2[nt][0]);
            u_q2c[r * SA + cI + 1]       = pack_bf(unpack_bf(u_v[r * SA + cI + 1]) * acc2[nt][1]);
            u_q2c[(r + 8) * SA + cI]     = pack_bf(unpack_bf(u_v[(r + 8) * SA + cI]) * acc2[nt][2]);
            u_q2c[(r + 8) * SA + cI + 1] = pack_bf(unpack_bf(u_v[(r + 8) * SA + cI + 1]) * acc2[nt][3]);
        }
    }
    for (int i = tid; i < CT * DD; i += NTHR) {
        int a_ = (i >> 7) * SA + (i & 127);
        u_sc[a_] = pack_bf(unpack_bf(u_v[a_]) * unpack_bf(u_c2q[a_]));
    }
    // init output accumulator with pproj
#pragma unroll
    for (int nt = 0; nt < 4; nt++) {
        int d = wc0 + nt * 8 + 2 * tg;
        float p0 = g_pproj[b * DD + d], p1 = g_pproj[b * DD + d + 1];
        oacc[nt][0] = p0; oacc[nt][1] = p1;
        oacc[nt][2] = p0; oacc[nt][3] = p1;
    }
    SLOT(4, u_v, oacc)
    SLOT(5, u_v, oacc)
    SLOT(6, u_c2q, oacc)
    SLOT(7, u_c2q, oacc)
    SLOT(8, u_sc, oacc)
    SLOT(9, u_sc, oacc)
    SLOT(10, u_q2c, oacc)
    SLOT(11, u_q2c, oacc)

    // epilogue: relu + store
    {
        int r = wr0 + gr;
#pragma unroll
        for (int nt = 0; nt < 4; nt++) {
            int d = wc0 + nt * 8 + 2 * tg;
            float* d0 = out + ((size_t)(b * CC + c0 + r)) * DD + d;
            float* d1 = out + ((size_t)(b * CC + c0 + r + 8)) * DD + d;
            *(float2*)d0 = make_float2(fmaxf(oacc[nt][0], 0.f), fmaxf(oacc[nt][1], 0.f));
            *(float2*)d1 = make_float2(fmaxf(oacc[nt][2], 0.f), fmaxf(oacc[nt][3], 0.f));
        }
    }
}

// ----------------------------------------------------------------------------
// Launch
// ----------------------------------------------------------------------------
extern "C" void kernel_launch(void* const* d_in, const int* in_sizes, int n_in,
                              void* d_out, int out_size) {
    const float* vfeats = (const float*)d_in[0];
    const float* qfeats = (const float*)d_in[1];
    const float* vmask  = (const float*)d_in[2];
    const float* qmask  = (const float*)d_in[3];
    const float* w4C    = (const float*)d_in[4];
    const float* w4Q    = (const float*)d_in[5];
    const float* w4mlu  = (const float*)d_in[6];
    const float* cqa_W  = (const float*)d_in[7];
    const float* cqa_b  = (const float*)d_in[8];
    const float* wp     = (const float*)d_in[9];
    const float* cc_W   = (const float*)d_in[10];
    const float* cc_b   = (const float*)d_in[11];
    float* out = (float*)d_out;

    const int SCORE_SMEM = (CT * SA + DD * SB) * (int)sizeof(unsigned);           // ~101 KB
    const int FUSED_SMEM = (4 * CT * SA + 2 * 64 * SB) * (int)sizeof(unsigned);   // ~200 KB
    cudaFuncSetAttribute(score_kernel, cudaFuncAttributeMaxDynamicSharedMemorySize, SCORE_SMEM);
    cudaFuncSetAttribute(fused_kernel, cudaFuncAttributeMaxDynamicSharedMemorySize, FUSED_SMEM);

    prep_G<<<4 * DD, DD>>>(cqa_W, cc_W);
    prep_qf<<<(BB * DD * QQ + 255) / 256, 256>>>(qfeats);
    prep_vf_rc<<<BB * CC / 8, 256>>>(vfeats, w4mlu, w4C);
    prep_cq<<<BB * QQ / 8, 256>>>(qfeats, w4Q);
    zero_k<<<(BB * QQ * DD + 255) / 256, 256>>>();
    pooled_kernel<<<BB, QQ>>>(qfeats, qmask, wp, cc_W, cc_b, cqa_b);
    score_kernel<<<dim3(CC / CT, BB), NTHR, SCORE_SMEM>>>(vmask);
    mid_kernel<<<dim3(BB, NSPLIT), NTHR>>>(vmask);
    pack_mid<<<(BB * QQ * DD + 255) / 256, 256>>>();
    fused_kernel<<<dim3(CC / CT, BB), NTHR, FUSED_SMEM>>>(qmask, out);
}

// round 17
// speedup vs baseline: 1.0677x; 1.0677x over previous
#include <cuda_runtime.h>
#include <cuda_bf16.h>
#include <math.h>

#define BB 64
#define CC 2048
#define QQ 128
#define DD 128
#define CT 64
#define NSPLIT 4
#define MASKV (-1e30f)
#define SA 132    // packed A-tile word stride
#define SB 136    // packed B-tile word stride (full 128-k rows)
#define SBH 72    // packed B half-tile word stride (64-k rows)
#define SMA 18    // mid stT word stride

// ----------------------------------------------------------------------------
// Device scratch
// ----------------------------------------------------------------------------
__device__ float    g_score[(size_t)BB * CC * QQ];  // E = exp(raw score)
__device__ float    g_rc[BB * CC];
__device__ float    g_cq[BB * QQ];
__device__ float    g_colsum[BB * QQ];
__device__ float    g_mid[BB * QQ * DD];
__device__ float    g_pproj[BB * DD];               // pooled proj + cqa_b@ccW1.T + cc_b
__device__ unsigned g_midpT[BB * DD * QQ];          // packed (mid/colsum), [b][d][q]
__device__ unsigned g_qfTp[BB * DD * QQ];           // packed qfeats^T [b][d][q]
__device__ unsigned g_qfp[BB * QQ * DD];            // packed qfeats  [b][q][d]
__device__ unsigned g_vfp[(size_t)BB * CC * DD];    // packed vfeats
__device__ unsigned g_vmlup[(size_t)BB * CC * DD];  // packed vfeats*w4mlu
__device__ unsigned g_GWpT[4 * DD * DD];            // packed G^T: [part][n=d][k]

// ----------------------------------------------------------------------------
// bf16-split helpers
// ----------------------------------------------------------------------------
__device__ __forceinline__ unsigned pack_bf(float x) {
    unsigned h = (unsigned)__bfloat16_as_ushort(__float2bfloat16(x));
    float hf = __uint_as_float(h << 16);
    unsigned l = (unsigned)__bfloat16_as_ushort(__float2bfloat16(x - hf));
    return h | (l << 16);
}

__device__ __forceinline__ float unpack_bf(unsigned w) {
    return __uint_as_float(w << 16) + __uint_as_float(w & 0xffff0000u);
}

__device__ __forceinline__ void mma_bf16(float c[4], const unsigned a[4], const unsigned b[2]) {
    asm volatile(
        "mma.sync.aligned.m16n8k16.row.col.f32.bf16.bf16.f32 "
        "{%0,%1,%2,%3}, {%4,%5,%6,%7}, {%8,%9}, {%0,%1,%2,%3};"
        : "+f"(c[0]), "+f"(c[1]), "+f"(c[2]), "+f"(c[3])
        : "r"(a[0]), "r"(a[1]), "r"(a[2]), "r"(a[3]), "r"(b[0]), "r"(b[1]));
}

__device__ __forceinline__ unsigned s2u(const void* p) {
    unsigned r;
    asm("{.reg .u64 t; cvta.to.shared.u64 t, %1; cvt.u32.u64 %0, t;}" : "=r"(r) : "l"(p));
    return r;
}
__device__ __forceinline__ void cp16(unsigned smaddr, const void* g) {
    asm volatile("cp.async.cg.shared.global [%0], [%1], 16;" :: "r"(smaddr), "l"(g));
}
#define CP_COMMIT() asm volatile("cp.async.commit_group;" ::: "memory")
#define CP_WAIT1()  asm volatile("cp.async.wait_group 1;" ::: "memory")

// A row-major [m][k] stride SAs (koffA applied); B **n-major** [n][k] stride SBs
// (koffB applied). Vectorized uint2 fragment loads on both operands.
template <int NT, int SAs, int SBs, int K>
__device__ __forceinline__ void mma_stage_t(const unsigned* __restrict__ A,
                                            const unsigned* __restrict__ B,
                                            float acc[2][NT][4],
                                            int wr0, int wc0, int lane,
                                            int koffA, int koffB) {
    const int gr = lane >> 2, t2 = (lane & 3) * 2;
#pragma unroll
    for (int k0 = 0; k0 < K; k0 += 16) {
        unsigned ah[2][4], al[2][4];
#pragma unroll
        for (int rb = 0; rb < 2; rb++) {
            const unsigned* p0 = A + (wr0 + rb * 16 + gr) * SAs + koffA + k0 + t2;
            const unsigned* p1 = A + (wr0 + rb * 16 + 8 + gr) * SAs + koffA + k0 + t2;
            uint2 wa = *(const uint2*)p0;
            uint2 wb = *(const uint2*)p1;
            uint2 wc = *(const uint2*)(p0 + 8);
            uint2 wd = *(const uint2*)(p1 + 8);
            ah[rb][0] = __byte_perm(wa.x, wa.y, 0x5410); al[rb][0] = __byte_perm(wa.x, wa.y, 0x7632);
            ah[rb][1] = __byte_perm(wb.x, wb.y, 0x5410); al[rb][1] = __byte_perm(wb.x, wb.y, 0x7632);
            ah[rb][2] = __byte_perm(wc.x, wc.y, 0x5410); al[rb][2] = __byte_perm(wc.x, wc.y, 0x7632);
            ah[rb][3] = __byte_perm(wd.x, wd.y, 0x5410); al[rb][3] = __byte_perm(wd.x, wd.y, 0x7632);
        }
#pragma unroll
        for (int nt = 0; nt < NT; nt++) {
            int n = wc0 + nt * 8 + gr;
            const unsigned* bp = B + n * SBs + koffB + k0 + t2;
            uint2 u0 = *(const uint2*)bp;
            uint2 u1 = *(const uint2*)(bp + 8);
            unsigned bh[2] = {__byte_perm(u0.x, u0.y, 0x5410), __byte_perm(u1.x, u1.y, 0x5410)};
            unsigned bl[2] = {__byte_perm(u0.x, u0.y, 0x7632), __byte_perm(u1.x, u1.y, 0x7632)};
#pragma unroll
            for (int rb = 0; rb < 2; rb++) {
                mma_bf16(acc[rb][nt], ah[rb], bh);
                mma_bf16(acc[rb][nt], al[rb], bh);
                mma_bf16(acc[rb][nt], ah[rb], bl);
            }
        }
    }
}

// k-major B variant (mid kernel only; B tile too small to be worth transposing)
template <int NT, int SAs, int SBs, int K>
__device__ __forceinline__ void mma_stage_k(const unsigned* __restrict__ A,
                                            const unsigned* __restrict__ B,
                                            float acc[2][NT][4],
                                            int wr0, int wc0, int lane) {
    const int gr = lane >> 2, t2 = (lane & 3) * 2;
#pragma unroll
    for (int k0 = 0; k0 < K; k0 += 16) {
        unsigned ah[2][4], al[2][4];
#pragma unroll
        for (int rb = 0; rb < 2; rb++) {
            const unsigned* p0 = A + (wr0 + rb * 16 + gr) * SAs + k0 + t2;
            const unsigned* p1 = A + (wr0 + rb * 16 + 8 + gr) * SAs + k0 + t2;
            uint2 wa = *(const uint2*)p0;
            uint2 wb = *(const uint2*)p1;
            uint2 wc = *(const uint2*)(p0 + 8);
            uint2 wd = *(const uint2*)(p1 + 8);
            ah[rb][0] = __byte_perm(wa.x, wa.y, 0x5410); al[rb][0] = __byte_perm(wa.x, wa.y, 0x7632);
            ah[rb][1] = __byte_perm(wb.x, wb.y, 0x5410); al[rb][1] = __byte_perm(wb.x, wb.y, 0x7632);
            ah[rb][2] = __byte_perm(wc.x, wc.y, 0x5410); al[rb][2] = __byte_perm(wc.x, wc.y, 0x7632);
            ah[rb][3] = __byte_perm(wd.x, wd.y, 0x5410); al[rb][3] = __byte_perm(wd.x, wd.y, 0x7632);
        }
#pragma unroll
        for (int nt = 0; nt < NT; nt++) {
            int n = wc0 + nt * 8 + gr;
            unsigned v0 = B[(k0 + t2) * SBs + n];
            unsigned v1 = B[(k0 + t2 + 1) * SBs + n];
            unsigned v2 = B[(k0 + 8 + t2) * SBs + n];
            unsigned v3 = B[(k0 + 9 + t2) * SBs + n];
            unsigned bh[2] = {__byte_perm(v0, v1, 0x5410), __byte_perm(v2, v3, 0x5410)};
            unsigned bl[2] = {__byte_perm(v0, v1, 0x7632), __byte_perm(v2, v3, 0x7632)};
#pragma unroll
            for (int rb = 0; rb < 2; rb++) {
                mma_bf16(acc[rb][nt], ah[rb], bh);
                mma_bf16(acc[rb][nt], al[rb], bh);
                mma_bf16(acc[rb][nt], ah[rb], bl);
            }
        }
    }
}

// ----------------------------------------------------------------------------
// Merged prep kernel: G^T, qf packs, cq, zero, pooled  (launch #1)
// ----------------------------------------------------------------------------
#define G_BLKS   (4 * DD)            // 512
#define QF_BLKS  (BB * DD * QQ / 256)
#define CQ_BLKS  (BB * QQ / 8)
#define ZK_BLKS  (BB * QQ * DD / 256)
__global__ void prep_misc(const float* __restrict__ qf, const float* __restrict__ qmask,
                          const float* __restrict__ w4Q, const float* __restrict__ wp,
                          const float* __restrict__ cqa_W, const float* __restrict__ cc_W,
                          const float* __restrict__ cc_b, const float* __restrict__ cqa_b) {
    __shared__ float s_buf[DD];
    __shared__ float s_al[QQ];
    __shared__ float s_pool[DD];
    int bx = blockIdx.x, t = threadIdx.x;

    if (bx < G_BLKS) {
        // G^T[part][d][k] = (ccW1 @ cqa_W)[d][part*DD+k]
        int col = bx;
        if (t < DD) s_buf[t] = cqa_W[t * (4 * DD) + col];
        __syncthreads();
        if (t < DD) {
            float s = 0.f;
#pragma unroll 4
            for (int j = 0; j < DD; j++) s += cc_W[t * (2 * DD) + j] * s_buf[j];
            int part = col >> 7, k = col & 127;
            g_GWpT[part * DD * DD + t * DD + k] = pack_bf(s);
        }
        return;
    }
    bx -= G_BLKS;
    if (bx < QF_BLKS) {
        int i = bx * 256 + t;
        int q = i % QQ;
        int r = i / QQ;
        int d = r % DD, b = r / DD;
        g_qfTp[i] = pack_bf(qf[((size_t)(b * QQ + q)) * DD + d]);
        g_qfp[i] = pack_bf(qf[i]);
        return;
    }
    bx -= QF_BLKS;
    if (bx < CQ_BLKS) {
        int row = bx * 8 + (t >> 5);
        int lane = t & 31;
        float4 v = *(const float4*)(qf + (size_t)row * DD + lane * 4);
        float4 w = *(const float4*)(w4Q + lane * 4);
        float s = v.x * w.x + v.y * w.y + v.z * w.z + v.w * w.w;
#pragma unroll
        for (int off = 16; off > 0; off >>= 1) s += __shfl_xor_sync(0xffffffffu, s, off);
        if (lane == 0) g_cq[row] = s;
        return;
    }
    bx -= CQ_BLKS;
    if (bx < ZK_BLKS) {
        int i = bx * 256 + t;
        g_mid[i] = 0.f;
        if (i < BB * QQ) g_colsum[i] = 0.f;
        return;
    }
    bx -= ZK_BLKS;
    // pooled: one block per batch b, active threads t < 128
    {
        int b = bx;
        bool act = t < QQ;
        float x = 0.f;
        if (act) {
            const float* row = qf + (size_t)(b * QQ + t) * DD;
#pragma unroll 4
            for (int d = 0; d < DD; d++) x += row[d] * wp[d];
            x += (1.f - qmask[b * QQ + t]) * MASKV;
            s_al[t] = x;
        }
        __syncthreads();
        for (int s = 64; s > 0; s >>= 1) {
            if (t < s) s_al[t] = fmaxf(s_al[t], s_al[t + s]);
            __syncthreads();
        }
        float m = s_al[0];
        __syncthreads();
        float e = 0.f;
        if (act) { e = __expf(x - m); s_al[t] = e; }
        __syncthreads();
        for (int s = 64; s > 0; s >>= 1) {
            if (t < s) s_al[t] += s_al[t + s];
            __syncthreads();
        }
        float inv = 1.f / s_al[0];
        __syncthreads();
        if (act) s_al[t] = e * inv;
        __syncthreads();
        if (act) {
            float p = 0.f;
#pragma unroll 4
            for (int q = 0; q < QQ; q++) p += s_al[q] * qf[(size_t)(b * QQ + q) * DD + t];
            s_pool[t] = p;
        }
        __syncthreads();
        if (act) {
            float o = cc_b[t];
#pragma unroll 4
            for (int k = 0; k < DD; k++) {
                o += s_pool[k] * cc_W[t * (2 * DD) + DD + k];
                o += cqa_b[k] * cc_W[t * (2 * DD) + k];
            }
            g_pproj[b * DD + t] = o;
        }
    }
}

// launch #2: pack vfeats + vfeats*mlu, and rc dot product (warp-per-row)
__global__ void prep_vf_rc(const float* __restrict__ vf, const float* __restrict__ w4mlu,
                           const float* __restrict__ w4C) {
    int row = blockIdx.x * 8 + (threadIdx.x >> 5);
    int lane = threadIdx.x & 31;
    float4 t = *(const float4*)(vf + (size_t)row * DD + lane * 4);
    float4 m = *(const float4*)(w4mlu + lane * 4);
    float4 w = *(const float4*)(w4C + lane * 4);
    unsigned* vp = g_vfp + (size_t)row * DD + lane * 4;
    unsigned* mp = g_vmlup + (size_t)row * DD + lane * 4;
    vp[0] = pack_bf(t.x); vp[1] = pack_bf(t.y); vp[2] = pack_bf(t.z); vp[3] = pack_bf(t.w);
    mp[0] = pack_bf(t.x * m.x); mp[1] = pack_bf(t.y * m.y);
    mp[2] = pack_bf(t.z * m.z); mp[3] = pack_bf(t.w * m.w);
    float s = t.x * w.x + t.y * w.y + t.z * w.z + t.w * w.w;
#pragma unroll
    for (int off = 16; off > 0; off >>= 1) s += __shfl_xor_sync(0xffffffffu, s, off);
    if (lane == 0) g_rc[row] = s;
}

// ----------------------------------------------------------------------------
// Score kernel (launch #3): E = exp(score), + masked column sums
// ----------------------------------------------------------------------------
__global__ __launch_bounds__(256) void score_kernel(const float* __restrict__ vmask) {
    extern __shared__ unsigned su[];
    unsigned* sAp = su;               // [64][SA]  A k-major
    unsigned* sBp = su + CT * SA;     // [128][SB] B n-major (= g_qfp rows)

    int b = blockIdx.y, c0 = blockIdx.x * CT, tid = threadIdx.x;

    {
        const uint4* srcA = (const uint4*)(g_vmlup + (size_t)(b * CC + c0) * DD);
        for (int i = tid; i < CT * DD / 4; i += 256)
            *(uint4*)&sAp[(i >> 5) * SA + (i & 31) * 4] = srcA[i];
        const uint4* srcB = (const uint4*)(g_qfp + (size_t)b * QQ * DD);
        for (int i = tid; i < QQ * DD / 4; i += 256)
            *(uint4*)&sBp[(i >> 5) * SB + (i & 31) * 4] = srcB[i];
    }
    __syncthreads();

    int warp = tid >> 5, lane = tid & 31;
    int gr = lane >> 2, tg = lane & 3;
    int wr0 = (warp & 1) * 32, wc0 = (warp >> 1) * 32;

    float acc[2][4][4];
#pragma unroll
    for (int rb = 0; rb < 2; rb++)
#pragma unroll
        for (int nt = 0; nt < 4; nt++)
#pragma unroll
            for (int j = 0; j < 4; j++) acc[rb][nt][j] = 0.f;

    mma_stage_t<4, SA, SB, 128>(sAp, sBp, acc, wr0, wc0, lane, 0, 0);

    float vm[4];
    vm[0] = vmask[b * CC + c0 + wr0 + gr];
    vm[1] = vmask[b * CC + c0 + wr0 + gr + 8];
    vm[2] = vmask[b * CC + c0 + wr0 + gr + 16];
    vm[3] = vmask[b * CC + c0 + wr0 + gr + 24];

#pragma unroll
    for (int rb = 0; rb < 2; rb++) {
        int r = wr0 + rb * 16 + gr;
        float rc0 = g_rc[b * CC + c0 + r];
        float rc1 = g_rc[b * CC + c0 + r + 8];
#pragma unroll
        for (int nt = 0; nt < 4; nt++) {
            int q = wc0 + nt * 8 + 2 * tg;
            float cq0 = g_cq[b * QQ + q], cq1 = g_cq[b * QQ + q + 1];
            acc[rb][nt][0] = __expf(acc[rb][nt][0] + rc0 + cq0);
            acc[rb][nt][1] = __expf(acc[rb][nt][1] + rc0 + cq1);
            acc[rb][nt][2] = __expf(acc[rb][nt][2] + rc1 + cq0);
            acc[rb][nt][3] = __expf(acc[rb][nt][3] + rc1 + cq1);
            float* d0 = g_score + ((size_t)(b * CC + c0 + r)) * QQ + q;
            float* d1 = g_score + ((size_t)(b * CC + c0 + r + 8)) * QQ + q;
            *(float2*)d0 = make_float2(acc[rb][nt][0], acc[rb][nt][1]);
            *(float2*)d1 = make_float2(acc[rb][nt][2], acc[rb][nt][3]);
        }
    }

#pragma unroll
    for (int nt = 0; nt < 4; nt++) {
#pragma unroll
        for (int j = 0; j < 2; j++) {
            float cs = acc[0][nt][j] * vm[0] + acc[0][nt][j + 2] * vm[1] +
                       acc[1][nt][j] * vm[2] + acc[1][nt][j + 2] * vm[3];
            cs += __shfl_xor_sync(0xffffffffu, cs, 4);
            cs += __shfl_xor_sync(0xffffffffu, cs, 8);
            cs += __shfl_xor_sync(0xffffffffu, cs, 16);
            if (lane < 4)
                atomicAdd(&g_colsum[b * QQ + wc0 + nt * 8 + 2 * tg + j], cs);
        }
    }
}

// ----------------------------------------------------------------------------
// mid (launch #4): mid[q,d] = sum_c E[c,q]*vmask[c]*v[c,d]
// ----------------------------------------------------------------------------
__global__ __launch_bounds__(256) void mid_kernel(const float* __restrict__ vmask) {
    __shared__ unsigned u_stT[QQ * SMA];
    __shared__ unsigned u_v[16 * SB];
    int b = blockIdx.x, sp = blockIdx.y, tid = threadIdx.x;
    int cbase = sp * (CC / NSPLIT);
    int warp = tid >> 5, lane = tid & 31;
    int gr = lane >> 2, tg = lane & 3;
    int wr0 = (warp & 3) * 32, wc0 = (warp >> 2) * 64;

    float acc[2][8][4];
#pragma unroll
    for (int rb = 0; rb < 2; rb++)
#pragma unroll
        for (int nt = 0; nt < 8; nt++)
#pragma unroll
            for (int j = 0; j < 4; j++) acc[rb][nt][j] = 0.f;

    for (int cc0 = 0; cc0 < CC / NSPLIT; cc0 += 16) {
        __syncthreads();
        for (int i = tid; i < 16 * QQ; i += 256) {
            int kc = i >> 7, col = i & 127;
            int c = cbase + cc0 + kc;
            float e = g_score[((size_t)(b * CC + c)) * QQ + col] * vmask[b * CC + c];
            u_stT[col * SMA + kc] = pack_bf(e);
        }
        const uint4* sv = (const uint4*)(g_vfp + (size_t)(b * CC + cbase + cc0) * DD);
        for (int i = tid; i < 16 * DD / 4; i += 256)
            *(uint4*)&u_v[(i >> 5) * SB + (i & 31) * 4] = sv[i];
        __syncthreads();
        mma_stage_k<8, SMA, SB, 16>(u_stT, u_v, acc, wr0, wc0, lane);
    }

#pragma unroll
    for (int rb = 0; rb < 2; rb++) {
        int q = wr0 + rb * 16 + gr;
#pragma unroll
        for (int nt = 0; nt < 8; nt++) {
            int d = wc0 + nt * 8 + 2 * tg;
            atomicAdd(&g_mid[(size_t)(b * QQ + q) * DD + d],     acc[rb][nt][0]);
            atomicAdd(&g_mid[(size_t)(b * QQ + q) * DD + d + 1], acc[rb][nt][1]);
            atomicAdd(&g_mid[(size_t)(b * QQ + q + 8) * DD + d],     acc[rb][nt][2]);
            atomicAdd(&g_mid[(size_t)(b * QQ + q + 8) * DD + d + 1], acc[rb][nt][3]);
        }
    }
}

// launch #5: scale + pack mid, TRANSPOSED to [b][d][q]
__global__ void pack_mid() {
    int i = blockIdx.x * blockDim.x + threadIdx.x;
    if (i >= BB * QQ * DD) return;
    int d = i & 127;
    int q = (i >> 7) & 127;
    int b = i >> 14;
    float v = g_mid[i] * (1.f / g_colsum[b * QQ + q]);
    g_midpT[((size_t)(b * DD + d)) * QQ + q] = pack_bf(v);
}

// ----------------------------------------------------------------------------
// Mega-fused (launch #6 — ncu capture slot): cp.async double-buffered B,
// 12 pipelined MMA slots over k-halves; B operands n-major (vectorized LDS).
// Slot s: matrix m = s>>1 (qfT, midT, G0..G3), k-half h = s&1.
// A per slot: [sc,sc, sc,sc, v,v, c2q,c2q, v*c2q,v*c2q, v*q2c,v*q2c]
// ----------------------------------------------------------------------------
__global__ __launch_bounds__(256, 1) void fused_kernel(const float* __restrict__ qmask,
                                                       float* __restrict__ out) {
    extern __shared__ unsigned su[];
    unsigned* u_sc  = su;                 // [64][SA] sc -> v*c2q
    unsigned* u_v   = u_sc + CT * SA;     // [64][SA]
    unsigned* u_c2q = u_v + CT * SA;      // [64][SA]
    unsigned* u_q2c = u_c2q + CT * SA;    // [64][SA] -> v*q2c
    unsigned* u_B   = u_q2c + CT * SA;    // 2 x [128][SBH] ping-pong (n-major, 64-k)

    int b = blockIdx.y;
    int c0 = blockIdx.x * CT;
    int tid = threadIdx.x;
    int warp = tid >> 5, lane = tid & 31;
    int gr = lane >> 2, tg = lane & 3;
    int wr0 = (warp & 1) * 32, wc0 = (warp >> 1) * 32;

    const unsigned* bsrcT[6];
    bsrcT[0] = g_qfTp + (size_t)b * DD * QQ;    // [d][q], k=q
    bsrcT[1] = g_midpT + (size_t)b * DD * QQ;   // [d][q], k=q
    bsrcT[2] = g_GWpT;
    bsrcT[3] = g_GWpT + DD * DD;
    bsrcT[4] = g_GWpT + 2 * DD * DD;
    bsrcT[5] = g_GWpT + 3 * DD * DD;

    // async fill of B k-half: 128 n-rows x 64 k-words
#define FILL_HALF(slot, buf)                                                     \
    {                                                                            \
        const unsigned* src_ = bsrcT[(slot) >> 1] + ((slot) & 1) * 64;           \
        unsigned* dstb_ = u_B + (buf) * (128 * SBH);                             \
        for (int i = tid; i < 128 * 64 / 4; i += 256) {                          \
            int n_ = i >> 4, kk = (i & 15) * 4;                                  \
            cp16(s2u(&dstb_[n_ * SBH + kk]), &src_[n_ * 128 + kk]);              \
        }                                                                        \
    }

    // Prologue
    {
        const unsigned* vs = g_vfp + (size_t)(b * CC + c0) * DD;
        for (int i = tid; i < CT * DD / 4; i += 256)
            cp16(s2u(&u_v[(i >> 5) * SA + (i & 31) * 4]), &vs[i * 4]);
        FILL_HALF(0, 0)
        CP_COMMIT();
        FILL_HALF(1, 1)
        CP_COMMIT();
    }

    // Phase 0: row softmax from E -> packed u_sc (overlaps async fills)
    {
        float qm[4];
#pragma unroll
        for (int j = 0; j < 4; j++) qm[j] = qmask[b * QQ + lane + 32 * j];
#pragma unroll
        for (int rr = 0; rr < 8; rr++) {
            int r = warp * 8 + rr;
            const float* src = g_score + ((size_t)(b * CC + c0 + r)) * QQ;
            float em[4];
            float s = 0.f;
#pragma unroll
            for (int j = 0; j < 4; j++) { em[j] = src[lane + 32 * j] * qm[j]; s += em[j]; }
#pragma unroll
            for (int off = 16; off > 0; off >>= 1)
                s += __shfl_xor_sync(0xffffffffu, s, off);
            float inv = 1.f / s;
#pragma unroll
            for (int j = 0; j < 4; j++)
                u_sc[r * SA + lane + 32 * j] = pack_bf(em[j] * inv);
        }
    }

#define ZERO_ACC(A_)                                      \
    _Pragma("unroll") for (int rb = 0; rb < 2; rb++)      \
    _Pragma("unroll") for (int nt = 0; nt < 4; nt++)      \
    _Pragma("unroll") for (int j = 0; j < 4; j++) A_[rb][nt][j] = 0.f;

#define PACK_ACC(DST, A_)                                                       \
    _Pragma("unroll") for (int rb = 0; rb < 2; rb++) {                          \
        int r_ = wr0 + rb * 16 + gr;                                            \
        _Pragma("unroll") for (int nt = 0; nt < 4; nt++) {                      \
            int cI = wc0 + nt * 8 + 2 * tg;                                     \
            (DST)[r_ * SA + cI]           = pack_bf(A_[rb][nt][0]);             \
            (DST)[r_ * SA + cI + 1]       = pack_bf(A_[rb][nt][1]);             \
            (DST)[(r_ + 8) * SA + cI]     = pack_bf(A_[rb][nt][2]);             \
            (DST)[(r_ + 8) * SA + cI + 1] = pack_bf(A_[rb][nt][3]);             \
        }                                                                       \
    }

    float acc1[2][4][4], acc2[2][4][4], oacc[2][4][4];
    ZERO_ACC(acc1)
    ZERO_ACC(acc2)

#define SLOT(i, Atile, ACC)                                                     \
    CP_WAIT1();                                                                 \
    __syncthreads();                                                            \
    mma_stage_t<4, SA, SBH, 64>(Atile, u_B + ((i) & 1) * (128 * SBH), ACC,      \
                                wr0, wc0, lane, ((i) & 1) * 64, 0);             \
    __syncthreads();                                                            \
    if ((i) + 2 < 12) { FILL_HALF((i) + 2, (i) & 1) }                           \
    CP_COMMIT();

    SLOT(0, u_sc, acc1)
    SLOT(1, u_sc, acc1)
    // c2q complete -> pack into u_c2q (read at slots 6,7; syncs intervene)
    PACK_ACC(u_c2q, acc1)
    SLOT(2, u_sc, acc2)
    SLOT(3, u_sc, acc2)
    // q2c complete: v*q2c from regs -> u_q2c; v*c2q pass -> u_sc (sc dead)
#pragma unroll
    for (int rb = 0; rb < 2; rb++) {
        int r = wr0 + rb * 16 + gr;
#pragma unroll
        for (int nt = 0; nt < 4; nt++) {
            int cI = wc0 + nt * 8 + 2 * tg;
            u_q2c[r * SA + cI]           = pack_bf(unpack_bf(u_v[r * SA + cI]) * acc2[rb][nt][0]);
            u_q2c[r * SA + cI + 1]       = pack_bf(unpack_bf(u_v[r * SA + cI + 1]) * acc2[rb][nt][1]);
            u_q2c[(r + 8) * SA + cI]     = pack_bf(unpack_bf(u_v[(r + 8) * SA + cI]) * acc2[rb][nt][2]);
            u_q2c[(r + 8) * SA + cI + 1] = pack_bf(unpack_bf(u_v[(r + 8) * SA + cI + 1]) * acc2[rb][nt][3]);
        }
    }
    for (int i = tid; i < CT * DD; i += 256) {
        int a_ = (i >> 7) * SA + (i & 127);
        u_sc[a_] = pack_bf(unpack_bf(u_v[a_]) * unpack_bf(u_c2q[a_]));
    }
    // init output accumulator with pproj
#pragma unroll
    for (int rb = 0; rb < 2; rb++)
#pragma unroll
        for (int nt = 0; nt < 4; nt++) {
            int d = wc0 + nt * 8 + 2 * tg;
            float p0 = g_pproj[b * DD + d], p1 = g_pproj[b * DD + d + 1];
            oacc[rb][nt][0] = p0; oacc[rb][nt][1] = p1;
            oacc[rb][nt][2] = p0; oacc[rb][nt][3] = p1;
        }
    SLOT(4, u_v, oacc)
    SLOT(5, u_v, oacc)
    SLOT(6, u_c2q, oacc)
    SLOT(7, u_c2q, oacc)
    SLOT(8, u_sc, oacc)
    SLOT(9, u_sc, oacc)
    SLOT(10, u_q2c, oacc)
    SLOT(11, u_q2c, oacc)

    // epilogue: relu + store
#pragma unroll
    for (int rb = 0; rb < 2; rb++) {
        int r = wr0 + rb * 16 + gr;
#pragma unroll
        for (int nt = 0; nt < 4; nt++) {
            int d = wc0 + nt * 8 + 2 * tg;
            float* d0 = out + ((size_t)(b * CC + c0 + r)) * DD + d;
            float* d1 = out + ((size_t)(b * CC + c0 + r + 8)) * DD + d;
            *(float2*)d0 = make_float2(fmaxf(oacc[rb][nt][0], 0.f), fmaxf(oacc[rb][nt][1], 0.f));
            *(float2*)d1 = make_float2(fmaxf(oacc[rb][nt][2], 0.f), fmaxf(oacc[rb][nt][3], 0.f));
        }
    }
}

// ----------------------------------------------------------------------------
// Launch: exactly 6 kernels; fused is launch #6 (ncu -s 5 -c 1 captures it)
// ----------------------------------------------------------------------------
extern "C" void kernel_launch(void* const* d_in, const int* in_sizes, int n_in,
                              void* d_out, int out_size) {
    const float* vfeats = (const float*)d_in[0];
    const float* qfeats = (const float*)d_in[1];
    const float* vmask  = (const float*)d_in[2];
    const float* qmask  = (const float*)d_in[3];
    const float* w4C    = (const float*)d_in[4];
    const float* w4Q    = (const float*)d_in[5];
    const float* w4mlu  = (const float*)d_in[6];
    const float* cqa_W  = (const float*)d_in[7];
    const float* cqa_b  = (const float*)d_in[8];
    const float* wp     = (const float*)d_in[9];
    const float* cc_W   = (const float*)d_in[10];
    const float* cc_b   = (const float*)d_in[11];
    float* out = (float*)d_out;

    const int SCORE_SMEM = (CT * SA + DD * SB) * (int)sizeof(unsigned);            // ~101 KB
    const int FUSED_SMEM = (4 * CT * SA + 2 * 128 * SBH) * (int)sizeof(unsigned);  // ~204 KB
    cudaFuncSetAttribute(score_kernel, cudaFuncAttributeMaxDynamicSharedMemorySize, SCORE_SMEM);
    cudaFuncSetAttribute(fused_kernel, cudaFuncAttributeMaxDynamicSharedMemorySize, FUSED_SMEM);

    int misc_blocks = G_BLKS + QF_BLKS + CQ_BLKS + ZK_BLKS + BB;
    prep_misc<<<misc_blocks, 256>>>(qfeats, qmask, w4Q, wp, cqa_W, cc_W, cc_b, cqa_b);
    prep_vf_rc<<<BB * CC / 8, 256>>>(vfeats, w4mlu, w4C);
    score_kernel<<<dim3(CC / CT, BB), 256, SCORE_SMEM>>>(vmask);
    mid_kernel<<<dim3(BB, NSPLIT), 256>>>(vmask);
    pack_mid<<<(BB * QQ * DD + 255) / 256, 256>>>();
    fused_kernel<<<dim3(CC / CT, BB), 256, FUSED_SMEM>>>(qmask, out);
}